// round 7
// baseline (speedup 1.0000x reference)
#include <cuda_runtime.h>
#include <cuda_bf16.h>
#include <stdint.h>
#include <math.h>

#define GAMMA 0.25f
#define RSTRIDE 528              // smem row pitch bytes (256 bf16 + 16B pad)
#define ATILE  67584             // 128 * RSTRIDE

// ---------------------------------------------------------------------------
// device scratch (static — no cudaMalloc allowed)
// ---------------------------------------------------------------------------
__device__ __align__(16) __nv_bfloat16 g_Bg[14 * 128 * 256];    // 14 B tiles [n][k]
__device__ __align__(16) __nv_bfloat16 g_qbf[65536 * 256];      // Q scratch bf16
__device__ __align__(16) __nv_bfloat16 g_kbf[65536 * 256];      // K scratch bf16

__device__ __forceinline__ uint32_t smem_u32(const void* p) {
    uint32_t a;
    asm("{ .reg .u64 t; cvta.to.shared.u64 t, %1; cvt.u32.u64 %0, t; }" : "=r"(a) : "l"(p));
    return a;
}

#define LDMX4(r0, r1, r2, r3, addr) \
    asm volatile("ldmatrix.sync.aligned.m8n8.x4.shared.b16 {%0,%1,%2,%3}, [%4];" \
                 : "=r"(r0), "=r"(r1), "=r"(r2), "=r"(r3) : "r"(addr))

#define MMA16816(d, a, b) \
    asm volatile("mma.sync.aligned.m16n8k16.row.col.f32.bf16.bf16.f32 " \
                 "{%0,%1,%2,%3}, {%4,%5,%6,%7}, {%8,%9}, {%0,%1,%2,%3};" \
                 : "+f"((d)[0]), "+f"((d)[1]), "+f"((d)[2]), "+f"((d)[3]) \
                 : "r"((a)[0]), "r"((a)[1]), "r"((a)[2]), "r"((a)[3]), \
                   "r"((b)[0]), "r"((b)[1]))

#define CPA16(dst, src) \
    asm volatile("cp.async.cg.shared.global [%0], [%1], 16;" :: "r"(dst), "l"(src) : "memory")
#define CPA_COMMIT() asm volatile("cp.async.commit_group;" ::: "memory")

// ---------------------------------------------------------------------------
__device__ __forceinline__ float block_reduce_256(float v, float* red) {
#pragma unroll
    for (int o = 16; o > 0; o >>= 1) v += __shfl_xor_sync(0xffffffffu, v, o);
    int w = threadIdx.x >> 5;
    if ((threadIdx.x & 31) == 0) red[w] = v;
    __syncthreads();
    if (threadIdx.x < 8) {
        v = red[threadIdx.x];
#pragma unroll
        for (int o = 4; o > 0; o >>= 1) v += __shfl_xor_sync(0x000000ffu, v, o);
    }
    return v;
}

// ---------------------------------------------------------------------------
// kprepB: build 14 dense bf16 B tiles [n][k] — one uint4 store per thread
// ---------------------------------------------------------------------------
extern "C" __global__ void __launch_bounds__(256)
kprepB(const float* __restrict__ Wm, const float* __restrict__ WQ,
       const float* __restrict__ WK, const float* __restrict__ We) {
    int nt = blockIdx.x;
    __nv_bfloat16* img = g_Bg + (size_t)nt * 128 * 256;
    int f0 = (blockIdx.y * 256 + threadIdx.x) * 8;   // grid.y = 16
    int n = f0 >> 8, k0 = f0 & 255;
    __nv_bfloat16 tmp[8];
#pragma unroll
    for (int i = 0; i < 8; i++) {
        int k = k0 + i;
        float v;
        if (nt < 8)        v = Wm[k * 1024 + nt * 128 + n];
        else if (nt < 10)  v = WQ[((nt - 8) * 128 + n) * 256 + k];
        else if (nt < 12)  v = WK[((nt - 10) * 128 + n) * 256 + k];
        else {
            int ng = (nt - 12) * 128 + n;
            v = (ng < 192) ? We[k * 192 + ng] : 0.f;
        }
        tmp[i] = __float2bfloat16(v);
    }
    *(uint4*)(img + f0) = *(uint4*)tmp;
}

// ---------------------------------------------------------------------------
// kgemm: single fused kernel. grid 512, 256 threads.
//   Phase 1: A (z rows of 2 batch elems) resident in smem; loop 14 N-tiles
//     with cp.async double-buffered B. Fused epilogues: phi_mem relu^2,
//     Q/K bf16 scratch stores, x-side (quad_x - phi_vis - phi_enc).
//   Phase 2: per batch elem, reload own Q/K (L2-hot) into the dead A region
//     and compute phi_att (8 warps = 8 heads, HMMA logits + LSE).
//   out[b] = complete energy.
// ---------------------------------------------------------------------------
extern "C" __global__ void __launch_bounds__(256, 1)
kgemm(const float* __restrict__ x, const float* __restrict__ z,
      const float* __restrict__ eb, const float* __restrict__ pos,
      const float* __restrict__ vb, float* __restrict__ out) {
    extern __shared__ char smem[];
    __shared__ float red[8], red2[8], mred[8];
    uint32_t sb = smem_u32(smem);
    const uint32_t As = sb;
    int tid = threadIdx.x, lane = tid & 31, w = tid >> 5;
    int wm = w >> 1, wn = w & 1;
    int mtile = blockIdx.x;

    // prefetch B tile 0 -> buf 0
    {
        const char* src = (const char*)(g_Bg);
#pragma unroll
        for (int i = 0; i < 16; i++) {
            int f = tid + i * 256;
            uint32_t dst = sb + ATILE + (f >> 5) * RSTRIDE + (f & 31) * 16;
            CPA16(dst, src + f * 16);
        }
        CPA_COMMIT();
    }

    // --- A load: z f32 -> bf16 smem + fused z statistics ---
    const float* zb = z + (size_t)mtile * 128 * 256;
    float zacc0 = 0.f, zacc1 = 0.f;
#pragma unroll
    for (int i = 0; i < 16; i++) {
        int f = tid + i * 256;               // chunk of 8 elems
        int row = f >> 5, c8 = (f & 31) * 8;
        const float4* zp = (const float4*)(zb + row * 256 + c8);
        float4 v0 = zp[0], v1 = zp[1];
        int prow = row & 63;
        float4 e0 = *(const float4*)(eb + c8);
        float4 e1 = *(const float4*)(eb + c8 + 4);
        float4 p0 = *(const float4*)(pos + prow * 256 + c8);
        float4 p1 = *(const float4*)(pos + prow * 256 + c8 + 4);
        float t =
            v0.x * (0.5f * v0.x - e0.x - p0.x) + v0.y * (0.5f * v0.y - e0.y - p0.y) +
            v0.z * (0.5f * v0.z - e0.z - p0.z) + v0.w * (0.5f * v0.w - e0.w - p0.w) +
            v1.x * (0.5f * v1.x - e1.x - p1.x) + v1.y * (0.5f * v1.y - e1.y - p1.y) +
            v1.z * (0.5f * v1.z - e1.z - p1.z) + v1.w * (0.5f * v1.w - e1.w - p1.w);
        if (i < 8) zacc0 += t; else zacc1 += t;
        uint4 pk;
        __nv_bfloat162 bt;
        bt = __floats2bfloat162_rn(v0.x, v0.y); pk.x = *(uint32_t*)&bt;
        bt = __floats2bfloat162_rn(v0.z, v0.w); pk.y = *(uint32_t*)&bt;
        bt = __floats2bfloat162_rn(v1.x, v1.y); pk.z = *(uint32_t*)&bt;
        bt = __floats2bfloat162_rn(v1.z, v1.w); pk.w = *(uint32_t*)&bt;
        *(uint4*)(smem + row * RSTRIDE + (f & 31) * 16) = pk;
    }

    // prefetch B tile 1 -> buf 1
    {
        const char* src = (const char*)(g_Bg + (size_t)128 * 256);
#pragma unroll
        for (int i = 0; i < 16; i++) {
            int f = tid + i * 256;
            uint32_t dst = sb + ATILE * 2 + (f >> 5) * RSTRIDE + (f & 31) * 16;
            CPA16(dst, src + f * 16);
        }
        CPA_COMMIT();
    }

    float msum = 0.f;          // phi_mem (subtract)
    float xsum = 0.f;          // quad_x - phi_vis - phi_enc (add)
    const float* xb = x + (size_t)mtile * 2 * 12288;
    int lrow = lane & 15, lhi = lane >> 4;

    for (int nt = 0; nt < 14; nt++) {
        uint32_t Bs = sb + ATILE + (uint32_t)(nt & 1) * ATILE;
        if (nt == 13) asm volatile("cp.async.wait_group 0;" ::: "memory");
        else          asm volatile("cp.async.wait_group 1;" ::: "memory");
        __syncthreads();

        float acc[2][8][4];
#pragma unroll
        for (int mi = 0; mi < 2; mi++)
#pragma unroll
            for (int nf = 0; nf < 8; nf++)
#pragma unroll
                for (int r = 0; r < 4; r++) acc[mi][nf][r] = 0.f;

#pragma unroll
        for (int ks = 0; ks < 16; ks++) {
            uint32_t coff = ks * 32 + lhi * 16;
            uint32_t a[2][4], b[4][4];
#pragma unroll
            for (int mi = 0; mi < 2; mi++) {
                uint32_t ad = As + (wm * 32 + mi * 16 + lrow) * RSTRIDE + coff;
                LDMX4(a[mi][0], a[mi][1], a[mi][2], a[mi][3], ad);
            }
#pragma unroll
            for (int bi = 0; bi < 4; bi++) {
                uint32_t bd = Bs + (wn * 64 + bi * 16 + lrow) * RSTRIDE + coff;
                LDMX4(b[bi][0], b[bi][1], b[bi][2], b[bi][3], bd);
            }
#pragma unroll
            for (int mi = 0; mi < 2; mi++)
#pragma unroll
                for (int bi = 0; bi < 4; bi++) {
                    uint32_t blo[2] = { b[bi][0], b[bi][2] };
                    uint32_t bhi[2] = { b[bi][1], b[bi][3] };
                    MMA16816(acc[mi][bi * 2 + 0], a[mi], blo);
                    MMA16816(acc[mi][bi * 2 + 1], a[mi], bhi);
                }
        }
        __syncthreads();   // all warps done reading buf (nt&1)

        // prefetch B[nt+2] into the buffer just freed
        if (nt + 2 < 14) {
            const char* src = (const char*)(g_Bg + (size_t)(nt + 2) * 128 * 256);
            uint32_t dstb = sb + ATILE + (uint32_t)(nt & 1) * ATILE;
#pragma unroll
            for (int i = 0; i < 16; i++) {
                int f = tid + i * 256;
                CPA16(dstb + (f >> 5) * RSTRIDE + (f & 31) * 16, src + f * 16);
            }
            CPA_COMMIT();
        }

        // ---- epilogue for this N-tile ----
        if (nt < 8) {
            // phi_mem: relu^2 reduce in-register
#pragma unroll
            for (int mi = 0; mi < 2; mi++)
#pragma unroll
                for (int nf = 0; nf < 8; nf++)
#pragma unroll
                    for (int r = 0; r < 4; r++) {
                        float v = fmaxf(acc[mi][nf][r], 0.f);
                        msum += v * v;
                    }
        } else if (nt < 12) {
            __nv_bfloat16* gout = (nt < 10) ? g_qbf : g_kbf;
            int tc = (nt < 10) ? (nt - 8) : (nt - 10);
            int colbase = tc * 128 + wn * 64 + (lane & 3) * 2;
            int rowbase = mtile * 128 + wm * 32 + (lane >> 2);
#pragma unroll
            for (int mi = 0; mi < 2; mi++)
#pragma unroll
                for (int nf = 0; nf < 8; nf++) {
                    int col = colbase + nf * 8;
                    int r0 = rowbase + mi * 16;
                    __nv_bfloat162 lo = __floats2bfloat162_rn(acc[mi][nf][0], acc[mi][nf][1]);
                    __nv_bfloat162 hi = __floats2bfloat162_rn(acc[mi][nf][2], acc[mi][nf][3]);
                    *(uint32_t*)(gout + (size_t)r0 * 256 + col) = *(uint32_t*)&lo;
                    *(uint32_t*)(gout + (size_t)(r0 + 8) * 256 + col) = *(uint32_t*)&hi;
                }
        } else {
            // enc tiles: consume accumulators directly against x (coalesced).
            // k = (nt-12)*128 + wn*64 + nf*8 + (lane&3)*2 + r  (valid k<192)
            int tc = nt - 12;
            if (!(tc == 1 && wn == 1)) {           // those cols are k>=192 (pad)
                int c = tc * 2 + wn;               // channel = k>>6
#pragma unroll
                for (int mi = 0; mi < 2; mi++)
#pragma unroll
                    for (int rp = 0; rp < 2; rp++) {
                        int l = wm * 32 + mi * 16 + rp * 8 + (lane >> 2);  // local row
                        int p = l & 63;
                        int jj = (p & 7) * 8 + (lane & 3) * 2;
                        size_t base0 = (size_t)(l >> 6) * 12288 + c * 4096 + (p >> 3) * 8 * 64 + jj;
#pragma unroll
                        for (int nf = 0; nf < 8; nf++) {
                            size_t off = base0 + nf * 64;  // ii = (p>>3)*8 + nf
                            float2 xv = *(const float2*)(xb + off);
                            float2 vv = *(const float2*)(vb + (off - (size_t)(l >> 6) * 12288));
                            float a0 = acc[mi][nf][rp * 2 + 0];
                            float a1 = acc[mi][nf][rp * 2 + 1];
                            xsum += xv.x * (0.5f * xv.x - vv.x - a0)
                                  + xv.y * (0.5f * xv.y - vv.y - a1);
                        }
                    }
            }
        }
    }

    // =========================================================================
    // Phase 2: attention (phi_att) for this CTA's own 2 batch elements.
    // A region is dead; Q -> rows 0..63, K -> rows 64..127 (pitch RSTRIDE).
    // Q/K were written by THIS CTA above; __syncthreads gives intra-CTA
    // global visibility; data is L2-hot.
    // =========================================================================
    float att0 = 0.f, att1 = 0.f;
#pragma unroll
    for (int bsel = 0; bsel < 2; bsel++) {
        __syncthreads();    // everyone done with A smem / Q,K stores visible
        const uint4* qsrc = (const uint4*)(g_qbf + (size_t)(mtile * 2 + bsel) * 64 * 256);
        const uint4* ksrc = (const uint4*)(g_kbf + (size_t)(mtile * 2 + bsel) * 64 * 256);
#pragma unroll
        for (int i = 0; i < 8; i++) {
            int c0 = tid + i * 256;          // 2048 chunks each
            int row = c0 >> 5, cc = (c0 & 31) * 16;
            *(uint4*)(smem + row * RSTRIDE + cc) = qsrc[c0];
            *(uint4*)(smem + (64 + row) * RSTRIDE + cc) = ksrc[c0];
        }
        __syncthreads();

        float attl = 0.f;
#pragma unroll
        for (int it = 0; it < 2; it++) {     // 32-row half of head w's 64 rows
            float aacc[2][8][4];
#pragma unroll
            for (int mf = 0; mf < 2; mf++)
#pragma unroll
                for (int nf = 0; nf < 8; nf++)
#pragma unroll
                    for (int r = 0; r < 4; r++) aacc[mf][nf][r] = 0.f;

#pragma unroll
            for (int kc = 0; kc < 2; kc++) {
                uint32_t coff = w * 64 + kc * 32 + lhi * 16;
                uint32_t a[2][4], bb[4][4];
#pragma unroll
                for (int mf = 0; mf < 2; mf++)
                    LDMX4(a[mf][0], a[mf][1], a[mf][2], a[mf][3],
                          As + (it * 32 + mf * 16 + lrow) * RSTRIDE + coff);
#pragma unroll
                for (int bi = 0; bi < 4; bi++)
                    LDMX4(bb[bi][0], bb[bi][1], bb[bi][2], bb[bi][3],
                          As + (64 + bi * 16 + lrow) * RSTRIDE + coff);
#pragma unroll
                for (int mf = 0; mf < 2; mf++)
#pragma unroll
                    for (int bi = 0; bi < 4; bi++) {
                        uint32_t blo[2] = { bb[bi][0], bb[bi][2] };
                        uint32_t bhi[2] = { bb[bi][1], bb[bi][3] };
                        MMA16816(aacc[mf][bi * 2 + 0], a[mf], blo);
                        MMA16816(aacc[mf][bi * 2 + 1], a[mf], bhi);
                    }
            }

            // row-wise LSE: each (mf, rl) row held by quad (lane&3)
#pragma unroll
            for (int mf = 0; mf < 2; mf++)
#pragma unroll
                for (int rl = 0; rl < 2; rl++) {
                    float amax = -1e30f;
#pragma unroll
                    for (int nf = 0; nf < 8; nf++) {
                        amax = fmaxf(amax, aacc[mf][nf][rl * 2 + 0]);
                        amax = fmaxf(amax, aacc[mf][nf][rl * 2 + 1]);
                    }
                    amax = fmaxf(amax, __shfl_xor_sync(0xffffffffu, amax, 1));
                    amax = fmaxf(amax, __shfl_xor_sync(0xffffffffu, amax, 2));
                    float se = 0.f;
#pragma unroll
                    for (int nf = 0; nf < 8; nf++) {
                        se += __expf(GAMMA * (aacc[mf][nf][rl * 2 + 0] - amax));
                        se += __expf(GAMMA * (aacc[mf][nf][rl * 2 + 1] - amax));
                    }
                    se += __shfl_xor_sync(0xffffffffu, se, 1);
                    se += __shfl_xor_sync(0xffffffffu, se, 2);
                    if ((lane & 3) == 0) attl += amax + __logf(se) * (1.f / GAMMA);
                }
        }
        if (bsel == 0) att0 = attl; else att1 = attl;
    }

    // ---- final per-batch reductions ----
    float wsum = xsum - msum;          // per-warp batch = wm>>1
#pragma unroll
    for (int o = 16; o > 0; o >>= 1) wsum += __shfl_xor_sync(0xffffffffu, wsum, o);
    if (lane == 0) mred[w] = wsum;
    float t0 = block_reduce_256(zacc0 - att0, red);
    float t1 = block_reduce_256(zacc1 - att1, red2);
    __syncthreads();
    if (tid == 0) {
        out[2 * mtile]     = t0 + (mred[0] + mred[1] + mred[2] + mred[3]);
        out[2 * mtile + 1] = t1 + (mred[4] + mred[5] + mred[6] + mred[7]);
    }
}

// ---------------------------------------------------------------------------
extern "C" void kernel_launch(void* const* d_in, const int* in_sizes, int n_in,
                              void* d_out, int out_size) {
    (void)in_sizes; (void)n_in; (void)out_size;
    const float* x   = (const float*)d_in[0];
    const float* z   = (const float*)d_in[1];
    const float* We  = (const float*)d_in[2];
    const float* ebv = (const float*)d_in[3];
    const float* vb  = (const float*)d_in[4];
    const float* pos = (const float*)d_in[5];
    const float* Wm  = (const float*)d_in[6];
    const float* WQ  = (const float*)d_in[7];
    const float* WK  = (const float*)d_in[8];
    float* out = (float*)d_out;

    size_t shg = (size_t)3 * ATILE;      // 202752 B

    cudaFuncSetAttribute(kgemm, cudaFuncAttributeMaxDynamicSharedMemorySize, (int)shg);

    kprepB<<<dim3(14, 16), 256>>>(Wm, WQ, WK, We);
    kgemm<<<512, 256, shg>>>(x, z, ebv, pos, vb, out);
}